// round 13
// baseline (speedup 1.0000x reference)
#include <cuda_runtime.h>
#include <cstdint>

// GaussianTrans via mma.sync tf32 (arch-agnostic PTX; tcgen05 is 'a'-gated).
//   outY[b,r,c,d] = sum_w sig(disY+attY) * V[b,w,c,d]   (pass Y: pure WRITE)
//   outX[b,r,c,d] = sum_h sig(disX+attX) * V[b,r,h,d]   (pass X: ACCUMULATE)
// B=16, H=W=64, D=512. Kernel body identical to R9 (best tf32 config:
// 64m x 64n x 64k CTA, 4 warps of 32m x 32n, 96 regs, 5 CTAs/SM, 2048-CTA
// launches). ONE structural change: pass order swapped so the strided pass (Y)
// only writes, and the RMW lands in pass X whose out slice is a contiguous
// 16KB/CTA stream served from L2 (dirty lines written by Y of same group).
// X/Y interleaved per 4 batches so V + out stay L2-resident within a group.

#define SK 68    // As row stride (pad 4): conflict-free frag loads
#define SN 72    // Vs row stride (pad 8): conflict-free frag loads

static constexpr uint32_t SMEM_BYTES = (64 * SK + 64 * SN) * 4;  // 35840

static __device__ __forceinline__ uint32_t tf32rn(float f) {
    uint32_t r;
    asm("cvt.rn.tf32.f32 %0, %1;" : "=r"(r) : "f"(f));
    return r;
}
static __device__ __forceinline__ float fast_sigmoid(float t) {
    return __fdividef(1.0f, 1.0f + __expf(-t));
}
static __device__ __forceinline__ void mma_tf32(float& c0, float& c1, float& c2,
                                                float& c3, uint32_t a0, uint32_t a1,
                                                uint32_t a2, uint32_t a3,
                                                uint32_t b0, uint32_t b1) {
    asm volatile(
        "mma.sync.aligned.m16n8k8.row.col.f32.tf32.tf32.f32 "
        "{%0,%1,%2,%3}, {%4,%5,%6,%7}, {%8,%9}, {%0,%1,%2,%3};"
        : "+f"(c0), "+f"(c1), "+f"(c2), "+f"(c3)
        : "r"(a0), "r"(a1), "r"(a2), "r"(a3), "r"(b0), "r"(b1));
}

template<bool PASSY, bool ACCUM>
__global__ __launch_bounds__(128, 5)
void gt_mma(const float* __restrict__ att, const float* __restrict__ V,
            float* __restrict__ out, const float* __restrict__ shift,
            const float* __restrict__ bias, int b0)
{
    extern __shared__ float smem[];
    float* As = smem;             // [64][SK], tf32-RN bit patterns
    float* Vs = smem + 64 * SK;   // [64][SN], raw fp32 (HW truncates to tf32)

    const int tid = threadIdx.x;
    const int dt    = blockIdx.x;          // 0..7 (d tile of 64)
    const int outer = blockIdx.y;          // r (pass X) or c (pass Y)
    const int b     = b0 + blockIdx.z;     // 4 batches per launch

    const float sh = shift[0], bi = bias[0];
    const int attBase = (b * 64 + outer) * 4096;
    const int off     = PASSY ? (b * 2097152 + outer * 512)
                              : ((b * 64 + outer) * 32768);
    const int vstride = PASSY ? 32768 : 512;
    const int dbase   = dt * 64;

    // --- A tile: sigmoid(dis + att) -> tf32-RN; coalesced float4 in ---
    #pragma unroll
    for (int j = 0; j < 8; ++j) {
        const int idx4 = tid + j * 128;          // 1024 float4 = 4096 elems
        const int m  = idx4 >> 4;
        const int k4 = (idx4 & 15) << 2;
        const float4 av = *reinterpret_cast<const float4*>(att + attBase + idx4 * 4);
        float d0 = (float)(k4 + 0 - m);
        float d1 = (float)(k4 + 1 - m);
        float d2 = (float)(k4 + 2 - m);
        float d3 = (float)(k4 + 3 - m);
        uint4 sv;
        sv.x = tf32rn(fast_sigmoid(fmaf(-sh * d0, d0, av.x - bi)));
        sv.y = tf32rn(fast_sigmoid(fmaf(-sh * d1, d1, av.y - bi)));
        sv.z = tf32rn(fast_sigmoid(fmaf(-sh * d2, d2, av.z - bi)));
        sv.w = tf32rn(fast_sigmoid(fmaf(-sh * d3, d3, av.w - bi)));
        *reinterpret_cast<uint4*>(&As[m * SK + k4]) = sv;
    }

    // --- V tile: 64 k-rows x 64 d, raw fp32 bits ---
    #pragma unroll
    for (int j = 0; j < 8; ++j) {
        const int idx4 = tid + j * 128;          // 1024 float4
        const int row  = idx4 >> 4;
        const int col  = (idx4 & 15) << 2;
        const float4 vv = *reinterpret_cast<const float4*>(
            V + off + row * vstride + dbase + col);
        *reinterpret_cast<float4*>(&Vs[row * SN + col]) = vv;
    }
    __syncthreads();

    // --- mma.sync m16n8k8 tf32: warp = 32m x 32n (2 m-tiles x 4 n-tiles) ---
    const int wid  = tid >> 5;
    const int lane = tid & 31;
    const int grp  = lane >> 2;     // 0..7
    const int tig  = lane & 3;      // 0..3
    const int mrow = (wid & 1) * 32;
    const int n0   = (wid >> 1) * 32;

    float acc[2][4][4];
    #pragma unroll
    for (int mt = 0; mt < 2; ++mt)
        #pragma unroll
        for (int nt = 0; nt < 4; ++nt)
            #pragma unroll
            for (int q = 0; q < 4; ++q) acc[mt][nt][q] = 0.0f;

    const uint32_t* Au = reinterpret_cast<const uint32_t*>(As);
    const uint32_t* Vu = reinterpret_cast<const uint32_t*>(Vs);

    #pragma unroll
    for (int k8 = 0; k8 < 8; ++k8) {
        const int kb = k8 * 8;
        uint32_t a[2][4];
        #pragma unroll
        for (int mt = 0; mt < 2; ++mt) {
            const int base = (mrow + mt * 16 + grp) * SK + kb + tig;
            a[mt][0] = Au[base];                 // (row,   col)
            a[mt][1] = Au[base + 8 * SK];        // (row+8, col)
            a[mt][2] = Au[base + 4];             // (row,   col+4)
            a[mt][3] = Au[base + 8 * SK + 4];    // (row+8, col+4)
        }
        #pragma unroll
        for (int nt = 0; nt < 4; ++nt) {
            const int nc = n0 + nt * 8 + grp;
            const uint32_t bq0 = Vu[(kb + tig) * SN + nc];
            const uint32_t bq1 = Vu[(kb + tig + 4) * SN + nc];
            #pragma unroll
            for (int mt = 0; mt < 2; ++mt)
                mma_tf32(acc[mt][nt][0], acc[mt][nt][1],
                         acc[mt][nt][2], acc[mt][nt][3],
                         a[mt][0], a[mt][1], a[mt][2], a[mt][3], bq0, bq1);
        }
    }

    // --- epilogue: Y writes; X accumulates (contiguous per-CTA out region) ---
    #pragma unroll
    for (int mt = 0; mt < 2; ++mt) {
        #pragma unroll
        for (int nt = 0; nt < 4; ++nt) {
            const int col  = dbase + n0 + nt * 8 + tig * 2;
            const int row0 = mrow + mt * 16 + grp;
            float* p0 = out + off + row0 * vstride + col;
            float* p1 = p0 + 8 * vstride;
            float2 w0 = make_float2(acc[mt][nt][0], acc[mt][nt][1]);
            float2 w1 = make_float2(acc[mt][nt][2], acc[mt][nt][3]);
            if (ACCUM) {
                const float2 o0 = *reinterpret_cast<const float2*>(p0);
                const float2 o1 = *reinterpret_cast<const float2*>(p1);
                w0.x += o0.x; w0.y += o0.y;
                w1.x += o1.x; w1.y += o1.y;
            }
            *reinterpret_cast<float2*>(p0) = w0;
            *reinterpret_cast<float2*>(p1) = w1;
        }
    }
}

extern "C" void kernel_launch(void* const* d_in, const int* in_sizes, int n_in,
                              void* d_out, int out_size) {
    (void)in_sizes; (void)n_in; (void)out_size;
    // metadata order: x(unused), attentionXFull, attentionYFull, valueFull, shift, bias
    const float* attX  = (const float*)d_in[1];
    const float* attY  = (const float*)d_in[2];
    const float* V     = (const float*)d_in[3];
    const float* shift = (const float*)d_in[4];
    const float* bias  = (const float*)d_in[5];
    float* out = (float*)d_out;

    cudaFuncSetAttribute((const void*)gt_mma<true, false>,
                         cudaFuncAttributeMaxDynamicSharedMemorySize, SMEM_BYTES);
    cudaFuncSetAttribute((const void*)gt_mma<false, true>,
                         cudaFuncAttributeMaxDynamicSharedMemorySize, SMEM_BYTES);

    dim3 grid(8, 64, 4);   // (d-tile of 64, outer, 4 batches) = 2048 CTAs
    dim3 block(128);
    // Per 4-batch group: Y first (pure write), then X (accumulate, L2-hot RMW).
    for (int b0 = 0; b0 < 16; b0 += 4) {
        gt_mma<true,  false><<<grid, block, SMEM_BYTES>>>(attY, V, out, shift, bias, b0);
        gt_mma<false, true ><<<grid, block, SMEM_BYTES>>>(attX, V, out, shift, bias, b0);
    }
}

// round 14
// speedup vs baseline: 1.2521x; 1.2521x over previous
#include <cuda_runtime.h>
#include <cstdint>

// GaussianTrans via mma.sync tf32 (arch-agnostic PTX; tcgen05 is 'a'-gated).
//   outX[b,r,c,d] = sum_h sig(disX+attX) * V[b,r,h,d]   (pass X: write)
//   outY[b,r,c,d] = sum_w sig(disY+attY) * V[b,w,c,d]   (pass Y: accumulate)
// B=16, H=W=64, D=512.
// R9 structure rebalanced for 32 warps/SM: CTA = 64m x 64n x 64k with 256
// threads = 8 warps of 16m x 32n (16 accs). 64 regs/thread -> 4 CTAs/SM =
// 1024 threads (reg-file limited), vs R9's 20 warps/SM. Same smem layout,
// same fills (rescaled), same X-then-Y 4-batch interleave for L2 reuse.

#define SK 68    // As row stride (pad 4): conflict-free frag loads
#define SN 72    // Vs row stride (pad 8): conflict-free frag loads

static constexpr uint32_t SMEM_BYTES = (64 * SK + 64 * SN) * 4;  // 35840

static __device__ __forceinline__ uint32_t tf32rn(float f) {
    uint32_t r;
    asm("cvt.rn.tf32.f32 %0, %1;" : "=r"(r) : "f"(f));
    return r;
}
static __device__ __forceinline__ float fast_sigmoid(float t) {
    return __fdividef(1.0f, 1.0f + __expf(-t));
}
static __device__ __forceinline__ void mma_tf32(float& c0, float& c1, float& c2,
                                                float& c3, uint32_t a0, uint32_t a1,
                                                uint32_t a2, uint32_t a3,
                                                uint32_t b0, uint32_t b1) {
    asm volatile(
        "mma.sync.aligned.m16n8k8.row.col.f32.tf32.tf32.f32 "
        "{%0,%1,%2,%3}, {%4,%5,%6,%7}, {%8,%9}, {%0,%1,%2,%3};"
        : "+f"(c0), "+f"(c1), "+f"(c2), "+f"(c3)
        : "r"(a0), "r"(a1), "r"(a2), "r"(a3), "r"(b0), "r"(b1));
}

template<bool PASSY>
__global__ __launch_bounds__(256, 4)
void gt_mma(const float* __restrict__ att, const float* __restrict__ V,
            float* __restrict__ out, const float* __restrict__ shift,
            const float* __restrict__ bias, int b0)
{
    extern __shared__ float smem[];
    float* As = smem;             // [64][SK], tf32-RN bit patterns
    float* Vs = smem + 64 * SK;   // [64][SN], raw fp32 (HW truncates to tf32)

    const int tid = threadIdx.x;
    const int dt    = blockIdx.x;          // 0..7 (d tile of 64)
    const int outer = blockIdx.y;          // r (pass X) or c (pass Y)
    const int b     = b0 + blockIdx.z;     // 4 batches per launch

    const float sh = shift[0], bi = bias[0];
    const int attBase = (b * 64 + outer) * 4096;
    const int off     = PASSY ? (b * 2097152 + outer * 512)
                              : ((b * 64 + outer) * 32768);
    const int vstride = PASSY ? 32768 : 512;
    const int dbase   = dt * 64;

    // --- A tile: sigmoid(dis + att) -> tf32-RN; coalesced float4 in ---
    #pragma unroll
    for (int j = 0; j < 4; ++j) {
        const int idx4 = tid + j * 256;          // 1024 float4 = 4096 elems
        const int m  = idx4 >> 4;
        const int k4 = (idx4 & 15) << 2;
        const float4 av = *reinterpret_cast<const float4*>(att + attBase + idx4 * 4);
        float d0 = (float)(k4 + 0 - m);
        float d1 = (float)(k4 + 1 - m);
        float d2 = (float)(k4 + 2 - m);
        float d3 = (float)(k4 + 3 - m);
        uint4 sv;
        sv.x = tf32rn(fast_sigmoid(fmaf(-sh * d0, d0, av.x - bi)));
        sv.y = tf32rn(fast_sigmoid(fmaf(-sh * d1, d1, av.y - bi)));
        sv.z = tf32rn(fast_sigmoid(fmaf(-sh * d2, d2, av.z - bi)));
        sv.w = tf32rn(fast_sigmoid(fmaf(-sh * d3, d3, av.w - bi)));
        *reinterpret_cast<uint4*>(&As[m * SK + k4]) = sv;
    }

    // --- V tile: 64 k-rows x 64 d, raw fp32 bits ---
    #pragma unroll
    for (int j = 0; j < 4; ++j) {
        const int idx4 = tid + j * 256;          // 1024 float4
        const int row  = idx4 >> 4;
        const int col  = (idx4 & 15) << 2;
        const float4 vv = *reinterpret_cast<const float4*>(
            V + off + row * vstride + dbase + col);
        *reinterpret_cast<float4*>(&Vs[row * SN + col]) = vv;
    }
    __syncthreads();

    // --- mma.sync m16n8k8 tf32: warp = 16m x 32n (4 n-tiles, 16 accs) ---
    const int wid  = tid >> 5;      // 0..7
    const int lane = tid & 31;
    const int grp  = lane >> 2;     // 0..7
    const int tig  = lane & 3;      // 0..3
    const int mrow = (wid & 3) * 16;
    const int n0   = (wid >> 2) * 32;

    float acc[4][4];
    #pragma unroll
    for (int nt = 0; nt < 4; ++nt)
        #pragma unroll
        for (int q = 0; q < 4; ++q) acc[nt][q] = 0.0f;

    const uint32_t* Au = reinterpret_cast<const uint32_t*>(As);
    const uint32_t* Vu = reinterpret_cast<const uint32_t*>(Vs);

    #pragma unroll
    for (int k8 = 0; k8 < 8; ++k8) {
        const int kb = k8 * 8;
        const int base = (mrow + grp) * SK + kb + tig;
        const uint32_t a0 = Au[base];               // (row,   col)
        const uint32_t a1 = Au[base + 8 * SK];      // (row+8, col)
        const uint32_t a2 = Au[base + 4];           // (row,   col+4)
        const uint32_t a3 = Au[base + 8 * SK + 4];  // (row+8, col+4)
        #pragma unroll
        for (int nt = 0; nt < 4; ++nt) {
            const int nc = n0 + nt * 8 + grp;
            const uint32_t bq0 = Vu[(kb + tig) * SN + nc];
            const uint32_t bq1 = Vu[(kb + tig + 4) * SN + nc];
            mma_tf32(acc[nt][0], acc[nt][1], acc[nt][2], acc[nt][3],
                     a0, a1, a2, a3, bq0, bq1);
        }
    }

    // --- epilogue: c0,c1 -> (row, 2 cols); c2,c3 -> (row+8, 2 cols) ---
    #pragma unroll
    for (int nt = 0; nt < 4; ++nt) {
        const int col  = dbase + n0 + nt * 8 + tig * 2;
        const int row0 = mrow + grp;
        float* p0 = out + off + row0 * vstride + col;
        float* p1 = p0 + 8 * vstride;
        float2 w0 = make_float2(acc[nt][0], acc[nt][1]);
        float2 w1 = make_float2(acc[nt][2], acc[nt][3]);
        if (PASSY) {
            const float2 o0 = *reinterpret_cast<const float2*>(p0);
            const float2 o1 = *reinterpret_cast<const float2*>(p1);
            w0.x += o0.x; w0.y += o0.y;
            w1.x += o1.x; w1.y += o1.y;
        }
        *reinterpret_cast<float2*>(p0) = w0;
        *reinterpret_cast<float2*>(p1) = w1;
    }
}

extern "C" void kernel_launch(void* const* d_in, const int* in_sizes, int n_in,
                              void* d_out, int out_size) {
    (void)in_sizes; (void)n_in; (void)out_size;
    // metadata order: x(unused), attentionXFull, attentionYFull, valueFull, shift, bias
    const float* attX  = (const float*)d_in[1];
    const float* attY  = (const float*)d_in[2];
    const float* V     = (const float*)d_in[3];
    const float* shift = (const float*)d_in[4];
    const float* bias  = (const float*)d_in[5];
    float* out = (float*)d_out;

    cudaFuncSetAttribute(gt_mma<false>,
                         cudaFuncAttributeMaxDynamicSharedMemorySize, SMEM_BYTES);
    cudaFuncSetAttribute(gt_mma<true>,
                         cudaFuncAttributeMaxDynamicSharedMemorySize, SMEM_BYTES);

    dim3 grid(8, 64, 4);   // (d-tile of 64, outer, 4 batches) = 2048 CTAs
    dim3 block(256);
    // Interleave per 4 batches: pass Y hits V[b] and outX[b] in L2.
    for (int b0 = 0; b0 < 16; b0 += 4) {
        gt_mma<false><<<grid, block, SMEM_BYTES>>>(attX, V, out, shift, bias, b0);
        gt_mma<true ><<<grid, block, SMEM_BYTES>>>(attY, V, out, shift, bias, b0);
    }
}

// round 15
// speedup vs baseline: 1.3043x; 1.0417x over previous
#include <cuda_runtime.h>
#include <cstdint>

// GaussianTrans via mma.sync tf32 (arch-agnostic PTX; tcgen05 is 'a'-gated).
//   outX[b,r,c,d] = sum_h sig(disX+attX) * V[b,r,h,d]   (X: write)
//   outY[b,r,c,d] = sum_w sig(disY+attY) * V[b,w,c,d]   (Y: accumulate)
// B=16, H=W=64, D=512.
// R13 kernel body unchanged (64m x 64n x 64k CTA, 8 warps of 16m x 32n,
// 64 regs, 4 CTAs/SM = 32 warps/SM). ONE schedule change: launches fused as
// X(group g) + Y(group g-1) -> 5 launches instead of 8, 4096-CTA mid-launches
// (6.9 waves, ~1% quantization). Y(g-1) reads outX(g-1) from the previous
// launch (stream-ordered) and finds V(g-1)/outX(g-1) in L2.

#define SK 68    // As row stride (pad 4): conflict-free frag loads
#define SN 72    // Vs row stride (pad 8): conflict-free frag loads

static constexpr uint32_t SMEM_BYTES = (64 * SK + 64 * SN) * 4;  // 35840

static __device__ __forceinline__ uint32_t tf32rn(float f) {
    uint32_t r;
    asm("cvt.rn.tf32.f32 %0, %1;" : "=r"(r) : "f"(f));
    return r;
}
static __device__ __forceinline__ float fast_sigmoid(float t) {
    return __fdividef(1.0f, 1.0f + __expf(-t));
}
static __device__ __forceinline__ void mma_tf32(float& c0, float& c1, float& c2,
                                                float& c3, uint32_t a0, uint32_t a1,
                                                uint32_t a2, uint32_t a3,
                                                uint32_t b0, uint32_t b1) {
    asm volatile(
        "mma.sync.aligned.m16n8k8.row.col.f32.tf32.tf32.f32 "
        "{%0,%1,%2,%3}, {%4,%5,%6,%7}, {%8,%9}, {%0,%1,%2,%3};"
        : "+f"(c0), "+f"(c1), "+f"(c2), "+f"(c3)
        : "r"(a0), "r"(a1), "r"(a2), "r"(a3), "r"(b0), "r"(b1));
}

__global__ __launch_bounds__(256, 4)
void gt_mma(const float* __restrict__ attX, const float* __restrict__ attY,
            const float* __restrict__ V, float* __restrict__ out,
            const float* __restrict__ shift, const float* __restrict__ bias,
            int bx0, int by0, int nx)
{
    extern __shared__ float smem[];
    float* As = smem;             // [64][SK], tf32-RN bit patterns
    float* Vs = smem + 64 * SK;   // [64][SN], raw fp32 (HW truncates to tf32)

    const int tid = threadIdx.x;
    const int dt    = blockIdx.x;          // 0..7 (d tile of 64)
    const int outer = blockIdx.y;          // r (pass X) or c (pass Y)
    const int z     = blockIdx.z;
    const bool passY = (z >= nx);
    const int b      = passY ? (by0 + z - nx) : (bx0 + z);
    const float* att = passY ? attY : attX;

    const float sh = shift[0], bi = bias[0];
    const int attBase = (b * 64 + outer) * 4096;
    const int off     = passY ? (b * 2097152 + outer * 512)
                              : ((b * 64 + outer) * 32768);
    const int vstride = passY ? 32768 : 512;
    const int dbase   = dt * 64;

    // --- A tile: sigmoid(dis + att) -> tf32-RN; coalesced float4 in ---
    #pragma unroll
    for (int j = 0; j < 4; ++j) {
        const int idx4 = tid + j * 256;          // 1024 float4 = 4096 elems
        const int m  = idx4 >> 4;
        const int k4 = (idx4 & 15) << 2;
        const float4 av = *reinterpret_cast<const float4*>(att + attBase + idx4 * 4);
        float d0 = (float)(k4 + 0 - m);
        float d1 = (float)(k4 + 1 - m);
        float d2 = (float)(k4 + 2 - m);
        float d3 = (float)(k4 + 3 - m);
        uint4 sv;
        sv.x = tf32rn(fast_sigmoid(fmaf(-sh * d0, d0, av.x - bi)));
        sv.y = tf32rn(fast_sigmoid(fmaf(-sh * d1, d1, av.y - bi)));
        sv.z = tf32rn(fast_sigmoid(fmaf(-sh * d2, d2, av.z - bi)));
        sv.w = tf32rn(fast_sigmoid(fmaf(-sh * d3, d3, av.w - bi)));
        *reinterpret_cast<uint4*>(&As[m * SK + k4]) = sv;
    }

    // --- V tile: 64 k-rows x 64 d, raw fp32 bits ---
    #pragma unroll
    for (int j = 0; j < 4; ++j) {
        const int idx4 = tid + j * 256;          // 1024 float4
        const int row  = idx4 >> 4;
        const int col  = (idx4 & 15) << 2;
        const float4 vv = *reinterpret_cast<const float4*>(
            V + off + row * vstride + dbase + col);
        *reinterpret_cast<float4*>(&Vs[row * SN + col]) = vv;
    }
    __syncthreads();

    // --- mma.sync m16n8k8 tf32: warp = 16m x 32n (4 n-tiles, 16 accs) ---
    const int wid  = tid >> 5;      // 0..7
    const int lane = tid & 31;
    const int grp  = lane >> 2;     // 0..7
    const int tig  = lane & 3;      // 0..3
    const int mrow = (wid & 3) * 16;
    const int n0   = (wid >> 2) * 32;

    float acc[4][4];
    #pragma unroll
    for (int nt = 0; nt < 4; ++nt)
        #pragma unroll
        for (int q = 0; q < 4; ++q) acc[nt][q] = 0.0f;

    const uint32_t* Au = reinterpret_cast<const uint32_t*>(As);
    const uint32_t* Vu = reinterpret_cast<const uint32_t*>(Vs);

    #pragma unroll
    for (int k8 = 0; k8 < 8; ++k8) {
        const int kb = k8 * 8;
        const int base = (mrow + grp) * SK + kb + tig;
        const uint32_t a0 = Au[base];               // (row,   col)
        const uint32_t a1 = Au[base + 8 * SK];      // (row+8, col)
        const uint32_t a2 = Au[base + 4];           // (row,   col+4)
        const uint32_t a3 = Au[base + 8 * SK + 4];  // (row+8, col+4)
        #pragma unroll
        for (int nt = 0; nt < 4; ++nt) {
            const int nc = n0 + nt * 8 + grp;
            const uint32_t bq0 = Vu[(kb + tig) * SN + nc];
            const uint32_t bq1 = Vu[(kb + tig + 4) * SN + nc];
            mma_tf32(acc[nt][0], acc[nt][1], acc[nt][2], acc[nt][3],
                     a0, a1, a2, a3, bq0, bq1);
        }
    }

    // --- epilogue: X writes; Y accumulates (outX from prior launch, L2-hot) ---
    #pragma unroll
    for (int nt = 0; nt < 4; ++nt) {
        const int col  = dbase + n0 + nt * 8 + tig * 2;
        const int row0 = mrow + grp;
        float* p0 = out + off + row0 * vstride + col;
        float* p1 = p0 + 8 * vstride;
        float2 w0 = make_float2(acc[nt][0], acc[nt][1]);
        float2 w1 = make_float2(acc[nt][2], acc[nt][3]);
        if (passY) {
            const float2 o0 = *reinterpret_cast<const float2*>(p0);
            const float2 o1 = *reinterpret_cast<const float2*>(p1);
            w0.x += o0.x; w0.y += o0.y;
            w1.x += o1.x; w1.y += o1.y;
        }
        *reinterpret_cast<float2*>(p0) = w0;
        *reinterpret_cast<float2*>(p1) = w1;
    }
}

extern "C" void kernel_launch(void* const* d_in, const int* in_sizes, int n_in,
                              void* d_out, int out_size) {
    (void)in_sizes; (void)n_in; (void)out_size;
    // metadata order: x(unused), attentionXFull, attentionYFull, valueFull, shift, bias
    const float* attX  = (const float*)d_in[1];
    const float* attY  = (const float*)d_in[2];
    const float* V     = (const float*)d_in[3];
    const float* shift = (const float*)d_in[4];
    const float* bias  = (const float*)d_in[5];
    float* out = (float*)d_out;

    cudaFuncSetAttribute(gt_mma, cudaFuncAttributeMaxDynamicSharedMemorySize,
                         SMEM_BYTES);

    dim3 block(256);
    // Pipelined schedule: launch i = X(group i) + Y(group i-1); 5 launches.
    // Y(b) reads outX(b) written by the PREVIOUS launch (stream-ordered).
    gt_mma<<<dim3(8, 64, 4), block, SMEM_BYTES>>>(attX, attY, V, out, shift, bias,
                                                  0, 0, 4);
    for (int g = 1; g < 4; ++g)
        gt_mma<<<dim3(8, 64, 8), block, SMEM_BYTES>>>(attX, attY, V, out, shift,
                                                      bias, g * 4, (g - 1) * 4, 4);
    gt_mma<<<dim3(8, 64, 4), block, SMEM_BYTES>>>(attX, attY, V, out, shift, bias,
                                                  0, 12, 0);
}